// round 1
// baseline (speedup 1.0000x reference)
#include <cuda_runtime.h>
#include <math.h>

// Problem constants
#define H 1024
#define H3 3072
#define SLEN 512
#define TLEN 512
#define VOCAB 32000

// GRU persistent kernel config
#define GRU_BLOCKS 148
#define GRU_THREADS 256

// ---------------- device scratch (no allocations allowed) ----------------
__device__ float g_enc_x[SLEN * H];
__device__ float g_dec_x[TLEN * H];
__device__ float g_gi0_enc[SLEN * H3];
__device__ float g_gi0_dec[TLEN * H3];
__device__ float g_gh0[H3];
__device__ float g_gq[2 * H3];
__device__ float g_dec_top[TLEN * H];
__device__ unsigned g_bar_count;
__device__ volatile unsigned g_bar_gen;

// ---------------- embedding gather ----------------
__global__ void gather_kernel(const int* __restrict__ src_tok,
                              const int* __restrict__ tgt_tok,
                              const float* __restrict__ src_emb,
                              const float* __restrict__ tgt_emb) {
    int t = blockIdx.x;
    int stok = src_tok[t];
    int dtok = (t == 0) ? 0 : tgt_tok[t - 1];
    const float* srow = src_emb + (size_t)stok * H;
    const float* drow = tgt_emb + (size_t)dtok * H;
    for (int i = threadIdx.x; i < H; i += blockDim.x) {
        g_enc_x[(size_t)t * H + i] = srow[i];
        g_dec_x[(size_t)t * H + i] = drow[i];
    }
}

// ---------------- generic C = A * B^T + bias GEMM ----------------
// A: [M,K] row-major, B: [N,K] row-major, C: [M,N]. M%128==0, N%128==0, K%16==0.
#define BM 128
#define BN 128
#define BK 16

__global__ __launch_bounds__(256) void gemm_nt_bias(
    const float* __restrict__ A, const float* __restrict__ B,
    const float* __restrict__ bias, float* __restrict__ C,
    int M, int N, int K) {
    __shared__ float As[BK][BM];
    __shared__ float Bs[BK][BN];
    int tid = threadIdx.x;
    int bm = blockIdx.y * BM;
    int bn = blockIdx.x * BN;
    int tx = tid & 15;
    int ty = tid >> 4;
    int m0 = ty * 8;
    int n0 = tx * 8;

    float acc[8][8];
#pragma unroll
    for (int i = 0; i < 8; ++i)
#pragma unroll
        for (int j = 0; j < 8; ++j) acc[i][j] = 0.f;

    for (int k0 = 0; k0 < K; k0 += BK) {
        // Load A tile (128 x 16) and B tile (128 x 16), transposed into smem.
#pragma unroll
        for (int it = 0; it < 2; ++it) {
            int idx = tid + it * 256;         // float4 index among 512
            int r = idx >> 2;                 // row within tile
            int c = (idx & 3) * 4;            // k within tile
            float4 va = *(const float4*)(A + (size_t)(bm + r) * K + k0 + c);
            As[c + 0][r] = va.x; As[c + 1][r] = va.y;
            As[c + 2][r] = va.z; As[c + 3][r] = va.w;
            float4 vb = *(const float4*)(B + (size_t)(bn + r) * K + k0 + c);
            Bs[c + 0][r] = vb.x; Bs[c + 1][r] = vb.y;
            Bs[c + 2][r] = vb.z; Bs[c + 3][r] = vb.w;
        }
        __syncthreads();
#pragma unroll
        for (int kk = 0; kk < BK; ++kk) {
            float a[8], b[8];
            *(float4*)(a)     = *(const float4*)(&As[kk][m0]);
            *(float4*)(a + 4) = *(const float4*)(&As[kk][m0 + 4]);
            *(float4*)(b)     = *(const float4*)(&Bs[kk][n0]);
            *(float4*)(b + 4) = *(const float4*)(&Bs[kk][n0 + 4]);
#pragma unroll
            for (int i = 0; i < 8; ++i)
#pragma unroll
                for (int j = 0; j < 8; ++j)
                    acc[i][j] = fmaf(a[i], b[j], acc[i][j]);
        }
        __syncthreads();
    }

    // Epilogue: add bias, store.
#pragma unroll
    for (int i = 0; i < 8; ++i) {
        float* crow = C + (size_t)(bm + m0 + i) * N + bn + n0;
#pragma unroll
        for (int j = 0; j < 8; ++j) crow[j] = acc[i][j] + bias[bn + n0 + j];
    }
}

// ---------------- GRU persistent kernel ----------------
__device__ __forceinline__ void grid_barrier() {
    __syncthreads();
    if (threadIdx.x == 0) {
        __threadfence();
        unsigned gen = g_bar_gen;
        if (atomicAdd(&g_bar_count, 1u) == (unsigned)(gridDim.x - 1)) {
            g_bar_count = 0u;
            __threadfence();
            g_bar_gen = gen + 1u;
        } else {
            while (g_bar_gen == gen) { __nanosleep(64); }
        }
        __threadfence();
    }
    __syncthreads();
}

__device__ __forceinline__ float warp_dot1024(const float* __restrict__ w,
                                              const float* __restrict__ xs,
                                              int lane) {
    const float4* w4 = (const float4*)w;
    const float4* x4 = (const float4*)xs;
    float s = 0.f;
#pragma unroll
    for (int it = 0; it < 8; ++it) {
        float4 a = w4[lane + it * 32];
        float4 b = x4[lane + it * 32];
        s = fmaf(a.x, b.x, s);
        s = fmaf(a.y, b.y, s);
        s = fmaf(a.z, b.z, s);
        s = fmaf(a.w, b.w, s);
    }
#pragma unroll
    for (int off = 16; off; off >>= 1)
        s += __shfl_xor_sync(0xffffffffu, s, off);
    return s;
}

__device__ __forceinline__ float sigmoidf_(float x) {
    return 1.0f / (1.0f + expf(-x));
}

__global__ __launch_bounds__(GRU_THREADS) void gru_seq_kernel(
    const float* __restrict__ eWih, const float* __restrict__ eWhh,
    const float* __restrict__ eBih, const float* __restrict__ eBhh,
    const float* __restrict__ dWih, const float* __restrict__ dWhh,
    const float* __restrict__ dBih, const float* __restrict__ dBhh) {
    __shared__ __align__(16) float h0[H];
    __shared__ __align__(16) float h1[H];
    int tid = threadIdx.x;
    int lane = tid & 31;
    int warp = tid >> 5;
    int gw = blockIdx.x * (GRU_THREADS / 32) + warp;
    int nw = gridDim.x * (GRU_THREADS / 32);

    for (int i = tid; i < H; i += GRU_THREADS) { h0[i] = 0.f; h1[i] = 0.f; }
    __syncthreads();

    for (int t = 0; t < SLEN + TLEN; ++t) {
        bool enc = (t < SLEN);
        const float* Whh0 = enc ? eWhh : dWhh;
        const float* Wih1 = (enc ? eWih : dWih) + (size_t)H3 * H;
        const float* Whh1 = (enc ? eWhh : dWhh) + (size_t)H3 * H;
        const float* bhh0 = enc ? eBhh : dBhh;
        const float* bih1 = (enc ? eBih : dBih) + H3;
        const float* bhh1 = (enc ? eBhh : dBhh) + H3;
        const float* gi0  = enc ? (g_gi0_enc + (size_t)t * H3)
                                : (g_gi0_dec + (size_t)(t - SLEN) * H3);

        // Phase A: gh0 = Whh0 @ h0 + bhh0
        for (int row = gw; row < H3; row += nw) {
            float s = warp_dot1024(Whh0 + (size_t)row * H, h0, lane);
            if (lane == 0) g_gh0[row] = s + bhh0[row];
        }
        grid_barrier();

        // Combine layer 0 (redundant per block -> h0 in smem)
        for (int j = tid; j < H; j += GRU_THREADS) {
            float r = sigmoidf_(gi0[j] + g_gh0[j]);
            float z = sigmoidf_(gi0[H + j] + g_gh0[H + j]);
            float n = tanhf(gi0[2 * H + j] + r * g_gh0[2 * H + j]);
            h0[j] = (1.f - z) * n + z * h0[j];
        }
        __syncthreads();

        // Phase B: gq[0:3H) = Wih1 @ h0 + bih1 ; gq[3H:6H) = Whh1 @ h1 + bhh1
        for (int row = gw; row < 2 * H3; row += nw) {
            float s;
            if (row < H3) {
                s = warp_dot1024(Wih1 + (size_t)row * H, h0, lane) + bih1[row];
            } else {
                int rr = row - H3;
                s = warp_dot1024(Whh1 + (size_t)rr * H, h1, lane) + bhh1[rr];
            }
            if (lane == 0) g_gq[row] = s;
        }
        grid_barrier();

        // Combine layer 1 (redundant per block -> h1 in smem)
        for (int j = tid; j < H; j += GRU_THREADS) {
            float r = sigmoidf_(g_gq[j] + g_gq[H3 + j]);
            float z = sigmoidf_(g_gq[H + j] + g_gq[H3 + H + j]);
            float n = tanhf(g_gq[2 * H + j] + r * g_gq[H3 + 2 * H + j]);
            float hnew = (1.f - z) * n + z * h1[j];
            h1[j] = hnew;
            if (!enc && blockIdx.x == 0)
                g_dec_top[(size_t)(t - SLEN) * H + j] = hnew;
        }
        __syncthreads();
    }
}

// ---------------- log_softmax (in-place per row) ----------------
__global__ __launch_bounds__(256) void logsoftmax_kernel(float* __restrict__ C, int N) {
    __shared__ float red[32];
    __shared__ float bcast;
    int row = blockIdx.x;
    float* x = C + (size_t)row * N;
    int tid = threadIdx.x;
    int lane = tid & 31, wid = tid >> 5;

    // max
    float m = -INFINITY;
    for (int i = tid; i < N; i += blockDim.x) m = fmaxf(m, x[i]);
#pragma unroll
    for (int o = 16; o; o >>= 1) m = fmaxf(m, __shfl_xor_sync(~0u, m, o));
    if (lane == 0) red[wid] = m;
    __syncthreads();
    if (wid == 0) {
        float v = (lane < (int)(blockDim.x >> 5)) ? red[lane] : -INFINITY;
#pragma unroll
        for (int o = 16; o; o >>= 1) v = fmaxf(v, __shfl_xor_sync(~0u, v, o));
        if (lane == 0) bcast = v;
    }
    __syncthreads();
    m = bcast;
    __syncthreads();

    // sum of exp
    float s = 0.f;
    for (int i = tid; i < N; i += blockDim.x) s += expf(x[i] - m);
#pragma unroll
    for (int o = 16; o; o >>= 1) s += __shfl_xor_sync(~0u, s, o);
    if (lane == 0) red[wid] = s;
    __syncthreads();
    if (wid == 0) {
        float v = (lane < (int)(blockDim.x >> 5)) ? red[lane] : 0.f;
#pragma unroll
        for (int o = 16; o; o >>= 1) v += __shfl_xor_sync(~0u, v, o);
        if (lane == 0) bcast = m + logf(v);
    }
    __syncthreads();
    float lse = bcast;

    for (int i = tid; i < N; i += blockDim.x) x[i] = x[i] - lse;
}

// ---------------- launch ----------------
extern "C" void kernel_launch(void* const* d_in, const int* in_sizes, int n_in,
                              void* d_out, int out_size) {
    const int*   src_tok = (const int*)d_in[0];
    const int*   tgt_tok = (const int*)d_in[1];
    const float* src_emb = (const float*)d_in[2];
    const float* tgt_emb = (const float*)d_in[3];
    const float* eWih = (const float*)d_in[4];
    const float* eWhh = (const float*)d_in[5];
    const float* eBih = (const float*)d_in[6];
    const float* eBhh = (const float*)d_in[7];
    const float* dWih = (const float*)d_in[8];
    const float* dWhh = (const float*)d_in[9];
    const float* dBih = (const float*)d_in[10];
    const float* dBhh = (const float*)d_in[11];
    const float* out_W = (const float*)d_in[12];
    const float* out_b = (const float*)d_in[13];
    float* out = (float*)d_out;

    // Resolve device-global scratch addresses.
    void *p_enc_x, *p_dec_x, *p_gi0_enc, *p_gi0_dec, *p_dec_top;
    cudaGetSymbolAddress(&p_enc_x, g_enc_x);
    cudaGetSymbolAddress(&p_dec_x, g_dec_x);
    cudaGetSymbolAddress(&p_gi0_enc, g_gi0_enc);
    cudaGetSymbolAddress(&p_gi0_dec, g_gi0_dec);
    cudaGetSymbolAddress(&p_dec_top, g_dec_top);

    // 1. Embedding gathers (encoder inputs + teacher-forced decoder inputs).
    gather_kernel<<<SLEN, 256>>>(src_tok, tgt_tok, src_emb, tgt_emb);

    // 2. Batched input-to-hidden projections for layer 0 (time-parallel).
    {
        dim3 grid(H3 / BN, SLEN / BM);
        gemm_nt_bias<<<grid, 256>>>((const float*)p_enc_x, eWih, eBih,
                                    (float*)p_gi0_enc, SLEN, H3, H);
        gemm_nt_bias<<<grid, 256>>>((const float*)p_dec_x, dWih, dBih,
                                    (float*)p_gi0_dec, TLEN, H3, H);
    }

    // 3. Sequential GRU scan (encoder 512 steps then decoder 512 steps),
    //    persistent kernel with grid barriers, hidden state held in SMEM.
    gru_seq_kernel<<<GRU_BLOCKS, GRU_THREADS>>>(eWih, eWhh, eBih, eBhh,
                                                dWih, dWhh, dBih, dBhh);

    // 4. Output projection: logits = dec_top @ out_W^T + out_b -> d_out.
    {
        dim3 grid(VOCAB / BN, TLEN / BM);
        gemm_nt_bias<<<grid, 256>>>((const float*)p_dec_top, out_W, out_b,
                                    out, TLEN, VOCAB, H);
    }

    // 5. In-place log_softmax over each row of 32000.
    logsoftmax_kernel<<<TLEN, 256>>>(out, VOCAB);
}

// round 2
// speedup vs baseline: 2.4328x; 2.4328x over previous
#include <cuda_runtime.h>
#include <math.h>

// Problem constants
#define H 1024
#define H3 3072
#define SLEN 512
#define TLEN 512
#define NSTEP (SLEN + TLEN)
#define VOCAB 32000

// GRU persistent kernel config
#define GRU_BLOCKS 148
#define GRU_THREADS 1024
#define WARPS_PER_BLK (GRU_THREADS / 32)
#define NW_TOT (GRU_BLOCKS * WARPS_PER_BLK)   // 4736 warps
#define ROWS_TOT (3 * H3)                     // 9216 rows per merged dot phase

// ---------------- device scratch (no allocations allowed) ----------------
__device__ float g_enc_x[SLEN * H];
__device__ float g_dec_x[TLEN * H];
__device__ float g_gi0_enc[SLEN * H3];
__device__ float g_gi0_dec[TLEN * H3];
__device__ float g_gA[2][H3];        // gh0 results (layer-0 hidden gates), double buffered
__device__ float g_gB[2][2 * H3];    // layer-1 gates [ih ; hh], double buffered
__device__ float g_dec_top[TLEN * H];
__device__ unsigned g_arrive[GRU_BLOCKS];
__device__ unsigned g_release;

// ---------------- embedding gather ----------------
__global__ void gather_kernel(const int* __restrict__ src_tok,
                              const int* __restrict__ tgt_tok,
                              const float* __restrict__ src_emb,
                              const float* __restrict__ tgt_emb) {
    int t = blockIdx.x;
    int stok = src_tok[t];
    int dtok = (t == 0) ? 0 : tgt_tok[t - 1];
    const float* srow = src_emb + (size_t)stok * H;
    const float* drow = tgt_emb + (size_t)dtok * H;
    for (int i = threadIdx.x; i < H; i += blockDim.x) {
        g_enc_x[(size_t)t * H + i] = srow[i];
        g_dec_x[(size_t)t * H + i] = drow[i];
    }
}

// ---------------- generic C = A * B^T + bias GEMM ----------------
#define BM 128
#define BN 128
#define BK 16

__global__ __launch_bounds__(256) void gemm_nt_bias(
    const float* __restrict__ A, const float* __restrict__ B,
    const float* __restrict__ bias, float* __restrict__ C,
    int M, int N, int K) {
    __shared__ float As[BK][BM];
    __shared__ float Bs[BK][BN];
    int tid = threadIdx.x;
    int bm = blockIdx.y * BM;
    int bn = blockIdx.x * BN;
    int tx = tid & 15;
    int ty = tid >> 4;
    int m0 = ty * 8;
    int n0 = tx * 8;

    float acc[8][8];
#pragma unroll
    for (int i = 0; i < 8; ++i)
#pragma unroll
        for (int j = 0; j < 8; ++j) acc[i][j] = 0.f;

    for (int k0 = 0; k0 < K; k0 += BK) {
#pragma unroll
        for (int it = 0; it < 2; ++it) {
            int idx = tid + it * 256;
            int r = idx >> 2;
            int c = (idx & 3) * 4;
            float4 va = *(const float4*)(A + (size_t)(bm + r) * K + k0 + c);
            As[c + 0][r] = va.x; As[c + 1][r] = va.y;
            As[c + 2][r] = va.z; As[c + 3][r] = va.w;
            float4 vb = *(const float4*)(B + (size_t)(bn + r) * K + k0 + c);
            Bs[c + 0][r] = vb.x; Bs[c + 1][r] = vb.y;
            Bs[c + 2][r] = vb.z; Bs[c + 3][r] = vb.w;
        }
        __syncthreads();
#pragma unroll
        for (int kk = 0; kk < BK; ++kk) {
            float a[8], b[8];
            *(float4*)(a)     = *(const float4*)(&As[kk][m0]);
            *(float4*)(a + 4) = *(const float4*)(&As[kk][m0 + 4]);
            *(float4*)(b)     = *(const float4*)(&Bs[kk][n0]);
            *(float4*)(b + 4) = *(const float4*)(&Bs[kk][n0 + 4]);
#pragma unroll
            for (int i = 0; i < 8; ++i)
#pragma unroll
                for (int j = 0; j < 8; ++j)
                    acc[i][j] = fmaf(a[i], b[j], acc[i][j]);
        }
        __syncthreads();
    }

#pragma unroll
    for (int i = 0; i < 8; ++i) {
        float* crow = C + (size_t)(bm + m0 + i) * N + bn + n0;
#pragma unroll
        for (int j = 0; j < 8; ++j) crow[j] = acc[i][j] + bias[bn + n0 + j];
    }
}

// ---------------- barrier primitives ----------------
__device__ __forceinline__ void st_release_u32(unsigned* p, unsigned v) {
    asm volatile("st.release.gpu.u32 [%0], %1;" :: "l"(p), "r"(v) : "memory");
}
__device__ __forceinline__ unsigned ld_acquire_u32(unsigned* p) {
    unsigned v;
    asm volatile("ld.acquire.gpu.u32 %0, [%1];" : "=r"(v) : "l"(p) : "memory");
    return v;
}

// One-aggregator flag barrier. gen must be unique & monotone within a launch,
// and the sequence must be identical across launches (graph replays).
__device__ __forceinline__ void grid_barrier(unsigned gen) {
    __syncthreads();
    int tid = threadIdx.x;
    if (blockIdx.x == 0) {
        if (tid > 0 && tid < GRU_BLOCKS) {
            while (ld_acquire_u32(&g_arrive[tid]) != gen) {}
        }
        __syncthreads();
        if (tid == 0) st_release_u32(&g_release, gen);
    } else {
        if (tid == 0) {
            st_release_u32(&g_arrive[blockIdx.x], gen);
            while (ld_acquire_u32(&g_release) != gen) {}
        }
        __syncthreads();
    }
}

// ---------------- warp dot product (1024 elems) ----------------
template <bool CG>
__device__ __forceinline__ float warp_dot1024(const float* __restrict__ w,
                                              const float* __restrict__ xs,
                                              int lane) {
    const float4* w4 = (const float4*)w;
    const float4* x4 = (const float4*)xs;
    float s = 0.f;
#pragma unroll
    for (int it = 0; it < 8; ++it) {
        float4 a = CG ? __ldcg(w4 + lane + it * 32) : __ldca(w4 + lane + it * 32);
        float4 b = x4[lane + it * 32];
        s = fmaf(a.x, b.x, s);
        s = fmaf(a.y, b.y, s);
        s = fmaf(a.z, b.z, s);
        s = fmaf(a.w, b.w, s);
    }
#pragma unroll
    for (int off = 16; off; off >>= 1)
        s += __shfl_xor_sync(0xffffffffu, s, off);
    return s;
}

__device__ __forceinline__ float sigmoidf_(float x) {
    return 1.0f / (1.0f + expf(-x));
}

// ---------------- GRU persistent kernel (1 barrier per step) ----------------
__global__ __launch_bounds__(GRU_THREADS, 1) void gru_seq_kernel(
    const float* __restrict__ eWih, const float* __restrict__ eWhh,
    const float* __restrict__ eBih, const float* __restrict__ eBhh,
    const float* __restrict__ dWih, const float* __restrict__ dWhh,
    const float* __restrict__ dBih, const float* __restrict__ dBhh) {
    __shared__ __align__(16) float h0[H];
    __shared__ __align__(16) float h1[H];
    int tid = threadIdx.x;
    int lane = tid & 31;
    int warp = tid >> 5;
    int gw = blockIdx.x * WARPS_PER_BLK + warp;

    h0[tid] = 0.f;
    h1[tid] = 0.f;
    // Prologue: gh0(0) = Whh0 @ 0 + bhh0 = bhh0. Every block writes the full
    // array redundantly (same values). Thread j writes exactly the elements it
    // later reads (j, H+j, 2H+j), so no cross-thread sync is needed.
    for (int r = tid; r < H3; r += GRU_THREADS) g_gA[0][r] = eBhh[r];
    __syncthreads();

    for (int t = 0; t < NSTEP; ++t) {
        int p = t & 1;
        bool enc_t = (t < SLEN);

        // ---- combine layer 1 for step t-1 (reads g_gB[1-p]) ----
        if (t > 0) {
            const float* gB = g_gB[1 - p];
            int j = tid;
            float ir = __ldcg(gB + j);
            float iz = __ldcg(gB + H + j);
            float in_ = __ldcg(gB + 2 * H + j);
            float hr = __ldcg(gB + H3 + j);
            float hz = __ldcg(gB + H3 + H + j);
            float hn = __ldcg(gB + H3 + 2 * H + j);
            float r = sigmoidf_(ir + hr);
            float z = sigmoidf_(iz + hz);
            float n = tanhf(in_ + r * hn);
            float hnew = (1.f - z) * n + z * h1[j];
            h1[j] = hnew;
            if (t - 1 >= SLEN && blockIdx.x == 0)
                g_dec_top[(size_t)(t - 1 - SLEN) * H + j] = hnew;
        }

        // ---- combine layer 0 for step t (reads g_gA[p], gi0(t)) ----
        {
            const float* gi = enc_t ? (g_gi0_enc + (size_t)t * H3)
                                    : (g_gi0_dec + (size_t)(t - SLEN) * H3);
            const float* gA = g_gA[p];
            int j = tid;
            float ga_r = __ldcg(gA + j);
            float ga_z = __ldcg(gA + H + j);
            float ga_n = __ldcg(gA + 2 * H + j);
            float gi_r = __ldcg(gi + j);
            float gi_z = __ldcg(gi + H + j);
            float gi_n = __ldcg(gi + 2 * H + j);
            float r = sigmoidf_(gi_r + ga_r);
            float z = sigmoidf_(gi_z + ga_z);
            float n = tanhf(gi_n + r * ga_n);
            h0[j] = (1.f - z) * n + z * h0[j];
        }
        __syncthreads();

        // ---- merged dot phase: B(t) rows [0,6144), A(t+1) rows [6144,9216) ----
        const float* Wih1 = (enc_t ? eWih : dWih) + (size_t)H3 * H;
        const float* Whh1 = (enc_t ? eWhh : dWhh) + (size_t)H3 * H;
        const float* bih1 = (enc_t ? eBih : dBih) + H3;
        const float* bhh1 = (enc_t ? eBhh : dBhh) + H3;
        bool encA = (t + 1 < SLEN);
        const float* Whh0n = encA ? eWhh : dWhh;
        const float* bhh0n = encA ? eBhh : dBhh;
        float* gBo = g_gB[p];
        float* gAo = g_gA[1 - p];

        // Round 0: row = gw (always < 4736 < 6144 -> a B row). L1-cached weights.
        {
            int row = gw;
            const float* w;
            const float* x;
            float b;
            if (row < H3) {
                w = Wih1 + (size_t)row * H; x = h0; b = bih1[row];
            } else {
                int rr = row - H3;
                w = Whh1 + (size_t)rr * H; x = h1; b = bhh1[rr];
            }
            float s = warp_dot1024<false>(w, x, lane);
            if (lane == 0) gBo[row] = s + b;
        }
        // Round 1: row = gw + 4736 (valid when < 9216). L2-only weights.
        {
            int row = gw + NW_TOT;
            if (row < ROWS_TOT) {
                if (row < 2 * H3) {
                    int rr = row - H3;
                    float s = warp_dot1024<true>(Whh1 + (size_t)rr * H, h1, lane);
                    if (lane == 0) gBo[row] = s + bhh1[rr];
                } else if (t + 1 < NSTEP) {
                    int rr = row - 2 * H3;
                    float s = warp_dot1024<true>(Whh0n + (size_t)rr * H, h0, lane);
                    if (lane == 0) gAo[rr] = s + bhh0n[rr];
                }
            }
        }

        grid_barrier((unsigned)(t + 1));
    }

    // Epilogue: combine layer 1 for final step (t-1 = 1023), block 0 only.
    if (blockIdx.x == 0) {
        const float* gB = g_gB[(NSTEP - 1) & 1];
        int j = tid;
        float ir = __ldcg(gB + j);
        float iz = __ldcg(gB + H + j);
        float in_ = __ldcg(gB + 2 * H + j);
        float hr = __ldcg(gB + H3 + j);
        float hz = __ldcg(gB + H3 + H + j);
        float hn = __ldcg(gB + H3 + 2 * H + j);
        float r = sigmoidf_(ir + hr);
        float z = sigmoidf_(iz + hz);
        float n = tanhf(in_ + r * hn);
        float hnew = (1.f - z) * n + z * h1[j];
        g_dec_top[(size_t)(TLEN - 1) * H + j] = hnew;
    }
}

// ---------------- log_softmax (in-place per row) ----------------
__global__ __launch_bounds__(256) void logsoftmax_kernel(float* __restrict__ C, int N) {
    __shared__ float red[32];
    __shared__ float bcast;
    int row = blockIdx.x;
    float* x = C + (size_t)row * N;
    int tid = threadIdx.x;
    int lane = tid & 31, wid = tid >> 5;

    float m = -INFINITY;
    for (int i = tid; i < N; i += blockDim.x) m = fmaxf(m, x[i]);
#pragma unroll
    for (int o = 16; o; o >>= 1) m = fmaxf(m, __shfl_xor_sync(~0u, m, o));
    if (lane == 0) red[wid] = m;
    __syncthreads();
    if (wid == 0) {
        float v = (lane < (int)(blockDim.x >> 5)) ? red[lane] : -INFINITY;
#pragma unroll
        for (int o = 16; o; o >>= 1) v = fmaxf(v, __shfl_xor_sync(~0u, v, o));
        if (lane == 0) bcast = v;
    }
    __syncthreads();
    m = bcast;
    __syncthreads();

    float s = 0.f;
    for (int i = tid; i < N; i += blockDim.x) s += expf(x[i] - m);
#pragma unroll
    for (int o = 16; o; o >>= 1) s += __shfl_xor_sync(~0u, s, o);
    if (lane == 0) red[wid] = s;
    __syncthreads();
    if (wid == 0) {
        float v = (lane < (int)(blockDim.x >> 5)) ? red[lane] : 0.f;
#pragma unroll
        for (int o = 16; o; o >>= 1) v += __shfl_xor_sync(~0u, v, o);
        if (lane == 0) bcast = m + logf(v);
    }
    __syncthreads();
    float lse = bcast;

    for (int i = tid; i < N; i += blockDim.x) x[i] = x[i] - lse;
}

// ---------------- launch ----------------
extern "C" void kernel_launch(void* const* d_in, const int* in_sizes, int n_in,
                              void* d_out, int out_size) {
    const int*   src_tok = (const int*)d_in[0];
    const int*   tgt_tok = (const int*)d_in[1];
    const float* src_emb = (const float*)d_in[2];
    const float* tgt_emb = (const float*)d_in[3];
    const float* eWih = (const float*)d_in[4];
    const float* eWhh = (const float*)d_in[5];
    const float* eBih = (const float*)d_in[6];
    const float* eBhh = (const float*)d_in[7];
    const float* dWih = (const float*)d_in[8];
    const float* dWhh = (const float*)d_in[9];
    const float* dBih = (const float*)d_in[10];
    const float* dBhh = (const float*)d_in[11];
    const float* out_W = (const float*)d_in[12];
    const float* out_b = (const float*)d_in[13];
    float* out = (float*)d_out;

    void *p_enc_x, *p_dec_x, *p_gi0_enc, *p_gi0_dec, *p_dec_top;
    cudaGetSymbolAddress(&p_enc_x, g_enc_x);
    cudaGetSymbolAddress(&p_dec_x, g_dec_x);
    cudaGetSymbolAddress(&p_gi0_enc, g_gi0_enc);
    cudaGetSymbolAddress(&p_gi0_dec, g_gi0_dec);
    cudaGetSymbolAddress(&p_dec_top, g_dec_top);

    // 1. Embedding gathers.
    gather_kernel<<<SLEN, 256>>>(src_tok, tgt_tok, src_emb, tgt_emb);

    // 2. Batched layer-0 input projections (time-parallel GEMMs).
    {
        dim3 grid(H3 / BN, SLEN / BM);
        gemm_nt_bias<<<grid, 256>>>((const float*)p_enc_x, eWih, eBih,
                                    (float*)p_gi0_enc, SLEN, H3, H);
        gemm_nt_bias<<<grid, 256>>>((const float*)p_dec_x, dWih, dBih,
                                    (float*)p_gi0_dec, TLEN, H3, H);
    }

    // 3. Sequential GRU scan: persistent kernel, one grid barrier per step.
    gru_seq_kernel<<<GRU_BLOCKS, GRU_THREADS>>>(eWih, eWhh, eBih, eBhh,
                                                dWih, dWhh, dBih, dBhh);

    // 4. Output projection.
    {
        dim3 grid(VOCAB / BN, TLEN / BM);
        gemm_nt_bias<<<grid, 256>>>((const float*)p_dec_top, out_W, out_b,
                                    out, TLEN, VOCAB, H);
    }

    // 5. In-place log_softmax.
    logsoftmax_kernel<<<TLEN, 256>>>(out, VOCAB);
}